// round 15
// baseline (speedup 1.0000x reference)
#include <cuda_runtime.h>
#include <cuda_fp16.h>
#include <cstdint>

// Problem constants
#define DM    1024          // d_model
#define HEADS 16
#define DK    64            // head dim
#define BB    4             // batch
#define SS    2048          // seq len
#define MTOT  (BB * SS)     // 8192 rows

// ---------------------------------------------------------------------------
// Scratch (device globals — no cudaMalloc allowed).
// NOTE (R7 lesson): tcgen05/TMEM unavailable — harness PTX target is sm_103
// (no 'a'). Legacy HMMA only.
// ---------------------------------------------------------------------------
__device__ __half g_xh[(size_t)MTOT * DM];      // x in fp16
__device__ __half g_Wh[4][(size_t)DM * DM];     // Wq, Wk, Wv, Wo in fp16
__device__ __half g_Qh[(size_t)MTOT * DM];      // (B,H,S,DK)
__device__ __half g_Kh[(size_t)MTOT * DM];      // (B,H,S,DK)
__device__ __half g_Vh[(size_t)MTOT * DM];      // (B,H,S,DK)
__device__ __half g_attnh[(size_t)MTOT * DM];   // (B,S,D)

// ---------------------------------------------------------------------------
// Helpers
// ---------------------------------------------------------------------------
__device__ __forceinline__ uint32_t h2u(__half2 h) {
    return *reinterpret_cast<uint32_t*>(&h);
}
__device__ __forceinline__ void cp_async16(void* smem_ptr, const void* gptr) {
    uint32_t sa = (uint32_t)__cvta_generic_to_shared(smem_ptr);
    asm volatile("cp.async.cg.shared.global [%0], [%1], 16;\n" :: "r"(sa), "l"(gptr));
}
__device__ __forceinline__ void cp_commit() {
    asm volatile("cp.async.commit_group;\n");
}
template <int N>
__device__ __forceinline__ void cp_wait() {
    asm volatile("cp.async.wait_group %0;\n" :: "n"(N));
}

// mma.m16n8k16 fp16: C(16x8,f32) += A(16x16,row) * B(16x8,col)
__device__ __forceinline__ void mma_f16(float c[4], const uint32_t a[4],
                                        uint32_t b0, uint32_t b1) {
    asm volatile(
        "mma.sync.aligned.m16n8k16.row.col.f32.f16.f16.f32 "
        "{%0,%1,%2,%3}, {%4,%5,%6,%7}, {%8,%9}, {%0,%1,%2,%3};"
        : "+f"(c[0]), "+f"(c[1]), "+f"(c[2]), "+f"(c[3])
        : "r"(a[0]), "r"(a[1]), "r"(a[2]), "r"(a[3]), "r"(b0), "r"(b1));
}

__device__ __forceinline__ void ldsm4(uint32_t r[4], uint32_t addr) {
    asm volatile("ldmatrix.sync.aligned.m8n8.x4.shared.b16 {%0,%1,%2,%3}, [%4];"
        : "=r"(r[0]), "=r"(r[1]), "=r"(r[2]), "=r"(r[3]) : "r"(addr));
}
__device__ __forceinline__ void ldsm4t(uint32_t r[4], uint32_t addr) {
    asm volatile("ldmatrix.sync.aligned.m8n8.x4.trans.shared.b16 {%0,%1,%2,%3}, [%4];"
        : "=r"(r[0]), "=r"(r[1]), "=r"(r[2]), "=r"(r[3]) : "r"(addr));
}
__device__ __forceinline__ uint32_t ex2_h2(uint32_t x) {
    uint32_t r;
    asm("ex2.approx.f16x2 %0, %1;" : "=r"(r) : "r"(x));
    return r;
}

// ---------------------------------------------------------------------------
// Conversions
// ---------------------------------------------------------------------------
__device__ __forceinline__ void cvt8(const float* __restrict__ src, __half* dst, int i)
{
    const float4* s4 = (const float4*)src;
    float4 v0 = s4[i * 2];
    float4 v1 = s4[i * 2 + 1];
    __half2 h[4];
    h[0] = __floats2half2_rn(v0.x, v0.y);
    h[1] = __floats2half2_rn(v0.z, v0.w);
    h[2] = __floats2half2_rn(v1.x, v1.y);
    h[3] = __floats2half2_rn(v1.z, v1.w);
    *(uint4*)&dst[(size_t)i * 8] = *(uint4*)h;
}

__global__ void f2h_x_kernel(const float* __restrict__ x, int n8)
{
    int i = blockIdx.x * blockDim.x + threadIdx.x;
    if (i < n8) cvt8(x, g_xh, i);
}

__global__ void f2h_w_kernel(const float* __restrict__ W0, const float* __restrict__ W1,
                             const float* __restrict__ W2, const float* __restrict__ W3)
{
    const int n8w = (DM * DM) / 8;
    int i = blockIdx.x * blockDim.x + threadIdx.x;
    int w = i / n8w, r = i - w * n8w;
    const float* src = (w == 0) ? W0 : (w == 1) ? W1 : (w == 2) ? W2 : W3;
    cvt8(src, g_Wh[w], r);
}

// ---------------------------------------------------------------------------
// GEMM v8 — 3-STAGE cp.async ring, ONE barrier per k-tile (CUTLASS invariant:
// buffer written at iter t was last read at iter t-1; the single end-of-iter
// barrier separates them). Raw mma + ldmatrix, register-double-buffered
// fragments, direct register epilogue. 128x128 block, KT=64, 8 warps,
// 2 CTAs/SM (SMEM 105KB/CTA).
// ---------------------------------------------------------------------------
#define KT       64
#define LDA_H    72
#define LDB_H    136
#define A_STG    (128 * LDA_H)
#define B_STG    (KT * LDB_H)
#define GEMM_SMEM_BYTES (3 * (A_STG + B_STG) * (int)sizeof(__half))

template <int MODE>
__global__ __launch_bounds__(256, 2)
void gemm_f16_kernel(const float* __restrict__ b0p,
                     const float* __restrict__ b1p,
                     const float* __restrict__ b2p,
                     float* __restrict__ Cout)
{
    extern __shared__ __half smh[];
    __half* As = smh;                // [3][A_STG]
    __half* Bs = smh + 3 * A_STG;    // [3][B_STG]

    const int z = blockIdx.z;
    const __half* A = (MODE == 0) ? (const __half*)g_attnh : (const __half*)g_xh;
    const __half* W = (MODE == 0) ? g_Wh[3] : g_Wh[z];
    const float* bias = (MODE == 0) ? b0p : (z == 0 ? b0p : (z == 1 ? b1p : b2p));
    __half* Ch = (MODE == 0) ? nullptr : (z == 0 ? g_Qh : (z == 1 ? g_Kh : g_Vh));

    const int tid  = threadIdx.x;
    const int warp = tid >> 5;
    const int lane = tid & 31;
    const int gr   = lane >> 2;
    const int gc   = lane & 3;
    const int wm   = warp >> 1;
    const int wn   = warp & 1;
    const int m0   = blockIdx.y * 128;
    const int n0   = blockIdx.x * 128;

    auto stage = [&](int buf, int k0) {
        __half* ad = As + buf * A_STG;
        __half* bd = Bs + buf * B_STG;
#pragma unroll
        for (int t = 0; t < 4; t++) {
            int id = tid + t * 256;
            int r = id >> 3, c = (id & 7) * 8;
            cp_async16(&ad[r * LDA_H + c], &A[(size_t)(m0 + r) * DM + k0 + c]);
        }
#pragma unroll
        for (int t = 0; t < 4; t++) {
            int id = tid + t * 256;
            int r = id >> 4, c = (id & 15) * 8;
            cp_async16(&bd[r * LDB_H + c], &W[(size_t)(k0 + r) * DM + n0 + c]);
        }
        cp_commit();
    };

    float acc[2][8][4];
#pragma unroll
    for (int im = 0; im < 2; im++)
#pragma unroll
        for (int nt = 0; nt < 8; nt++)
            acc[im][nt][0] = acc[im][nt][1] = acc[im][nt][2] = acc[im][nt][3] = 0.0f;

    const uint32_t as_addr = (uint32_t)__cvta_generic_to_shared(As);
    const uint32_t bs_addr = (uint32_t)__cvta_generic_to_shared(Bs);
    const uint32_t a_off = (((lane & 15) * LDA_H) + ((lane >> 4) * 8)) * 2;
    const uint32_t b_off = (((lane & 15) * LDB_H) + ((lane & 16) >> 1)) * 2;

    stage(0, 0);
    stage(1, KT);
    cp_wait<1>();        // tile 0 ready (tile 1 in flight)
    __syncthreads();

    uint32_t afr[2][2][4];
    uint32_t bfr[2][4][4];

    const int NT = DM / KT;   // 16
    for (int t = 0; t < NT; t++) {
        const int buf = t % 3;
        // prefetch tile t+2 into ring slot (t+2)%3 (= (t-1)%3, read finished
        // at iter t-1 and separated from this write by the end-of-(t-1) barrier)
        if (t + 2 < NT) stage((t + 2) % 3, (t + 2) * KT);

        const uint32_t abase = as_addr + buf * A_STG * 2 + a_off + (wm * 32 * LDA_H) * 2;
        const uint32_t bbase = bs_addr + buf * B_STG * 2 + b_off + (wn * 64) * 2;

        // preload ks=0 fragments
        ldsm4(afr[0][0], abase);
        ldsm4(afr[0][1], abase + (16 * LDA_H) * 2);
#pragma unroll
        for (int ntp = 0; ntp < 4; ntp++)
            ldsm4t(bfr[0][ntp], bbase + (ntp * 16) * 2);

#pragma unroll
        for (int ks = 0; ks < 4; ks++) {
            const int cur = ks & 1, nxt = cur ^ 1;
            if (ks < 3) {
                ldsm4(afr[nxt][0], abase + ((ks + 1) * 16) * 2);
                ldsm4(afr[nxt][1], abase + (16 * LDA_H + (ks + 1) * 16) * 2);
#pragma unroll
                for (int ntp = 0; ntp < 4; ntp++)
                    ldsm4t(bfr[nxt][ntp], bbase + ((ks + 1) * 16 * LDB_H + ntp * 16) * 2);
            }
#pragma unroll
            for (int ntp = 0; ntp < 4; ntp++) {
                mma_f16(acc[0][2 * ntp],     afr[cur][0], bfr[cur][ntp][0], bfr[cur][ntp][1]);
                mma_f16(acc[0][2 * ntp + 1], afr[cur][0], bfr[cur][ntp][2], bfr[cur][ntp][3]);
                mma_f16(acc[1][2 * ntp],     afr[cur][1], bfr[cur][ntp][0], bfr[cur][ntp][1]);
                mma_f16(acc[1][2 * ntp + 1], afr[cur][1], bfr[cur][ntp][2], bfr[cur][ntp][3]);
            }
        }

        if (t + 1 < NT) {
            if (t + 2 < NT) cp_wait<1>();   // tile t+1 done, t+2 in flight
            else            cp_wait<0>();   // last tile: drain all
            __syncthreads();                // the ONE barrier per iteration
        }
    }

    float bv0[8], bv1[8];
#pragma unroll
    for (int nt = 0; nt < 8; nt++) {
        int gn = n0 + wn * 64 + nt * 8 + gc * 2;
        bv0[nt] = bias[gn];
        bv1[nt] = bias[gn + 1];
    }

#pragma unroll
    for (int im = 0; im < 2; im++) {
        int gm0 = m0 + wm * 32 + im * 16 + gr;
        int gm1 = gm0 + 8;
        if (MODE == 0) {
            float* d0 = Cout + (size_t)gm0 * DM + n0 + wn * 64 + gc * 2;
            float* d1 = Cout + (size_t)gm1 * DM + n0 + wn * 64 + gc * 2;
#pragma unroll
            for (int nt = 0; nt < 8; nt++) {
                *(float2*)&d0[nt * 8] = make_float2(acc[im][nt][0] + bv0[nt],
                                                    acc[im][nt][1] + bv1[nt]);
                *(float2*)&d1[nt * 8] = make_float2(acc[im][nt][2] + bv0[nt],
                                                    acc[im][nt][3] + bv1[nt]);
            }
        } else {
            int h  = (n0 + wn * 64) >> 6;
            int b0i = gm0 >> 11, s0 = gm0 & 2047;
            int b1i = gm1 >> 11, s1 = gm1 & 2047;
            __half* d0 = Ch + (((size_t)(b0i * HEADS + h)) * SS + s0) * DK + gc * 2;
            __half* d1 = Ch + (((size_t)(b1i * HEADS + h)) * SS + s1) * DK + gc * 2;
#pragma unroll
            for (int nt = 0; nt < 8; nt++) {
                *(__half2*)&d0[nt * 8] = __floats2half2_rn(acc[im][nt][0] + bv0[nt],
                                                           acc[im][nt][1] + bv1[nt]);
                *(__half2*)&d1[nt * 8] = __floats2half2_rn(acc[im][nt][2] + bv0[nt],
                                                           acc[im][nt][3] + bv1[nt]);
            }
        }
    }
}

// ---------------------------------------------------------------------------
// Flash attention v8 — R11 shape (128 q-rows/CTA, 8 warps x 16 rows, 2 CTAs/
// SM) with a 3-STAGE K/V ring and ONE barrier per key-tile. ldmatrix,
// log2-softmax via ex2.approx.f16x2, l via ones-HMMA.
// ---------------------------------------------------------------------------
#define LDH    72
#define TILE_H (64 * LDH)
#define FLASH_SMEM_BYTES (6 * TILE_H * (int)sizeof(__half))   // 3 stages x (K+V)
#define ONES_H2 0x3C003C00u

__global__ __launch_bounds__(256, 2)
void flash_attn_kernel()
{
    extern __shared__ __half smf[];
    __half* KsB = smf;                 // [3][TILE_H]
    __half* VsB = smf + 3 * TILE_H;    // [3][TILE_H]

    const int tid  = threadIdx.x;
    const int warp = tid >> 5;
    const int lane = tid & 31;
    const int gr   = lane >> 2;
    const int gc   = lane & 3;
    const int qt   = blockIdx.x;
    const int bh   = blockIdx.y;

    const __half* Qb = g_Qh + (size_t)bh * SS * DK;
    const __half* Kb = g_Kh + (size_t)bh * SS * DK;
    const __half* Vb = g_Vh + (size_t)bh * SS * DK;

    const int qrow = qt * 128 + warp * 16;

    const __half2 sc2 = __float2half2_rn(0.125f * 1.4426950408889634f);
    uint32_t qa[4][4];
#pragma unroll
    for (int kk = 0; kk < 4; kk++) {
        const __half* q0 = Qb + (size_t)(qrow + gr)     * DK + kk * 16 + 2 * gc;
        const __half* q1 = Qb + (size_t)(qrow + gr + 8) * DK + kk * 16 + 2 * gc;
        qa[kk][0] = h2u(__hmul2(*(const __half2*)(q0),     sc2));
        qa[kk][1] = h2u(__hmul2(*(const __half2*)(q1),     sc2));
        qa[kk][2] = h2u(__hmul2(*(const __half2*)(q0 + 8), sc2));
        qa[kk][3] = h2u(__hmul2(*(const __half2*)(q1 + 8), sc2));
    }

    float o[8][4];
#pragma unroll
    for (int nt = 0; nt < 8; nt++) { o[nt][0] = o[nt][1] = o[nt][2] = o[nt][3] = 0.0f; }
    float lacc[4] = {0.0f, 0.0f, 0.0f, 0.0f};
    float m0 = -1e30f, m1 = -1e30f;

    const uint32_t ks_addr = (uint32_t)__cvta_generic_to_shared(KsB);
    const uint32_t vs_addr = (uint32_t)__cvta_generic_to_shared(VsB);
    const uint32_t qk_off = ((((lane & 7) | ((lane & 16) >> 1)) * LDH) + (lane & 8)) * 2;
    const uint32_t pv_off = (((lane & 15) * LDH) + ((lane & 16) >> 1)) * 2;

    auto stage = [&](int buf, int jt) {
        const __half* Kt = Kb + (size_t)(jt * 64) * DK;
        const __half* Vt = Vb + (size_t)(jt * 64) * DK;
        __half* kd = KsB + buf * TILE_H;
        __half* vd = VsB + buf * TILE_H;
#pragma unroll
        for (int rp = 0; rp < 2; rp++) {
            int id = tid + rp * 256;
            int row = id >> 3, c8 = (id & 7) * 8;
            cp_async16(&kd[row * LDH + c8], &Kt[(size_t)row * DK + c8]);
            cp_async16(&vd[row * LDH + c8], &Vt[(size_t)row * DK + c8]);
        }
        cp_commit();
    };

    stage(0, 0);
    stage(1, 1);
    cp_wait<1>();        // tile 0 ready
    __syncthreads();

    const int NT = SS / 64;   // 32
    for (int jt = 0; jt < NT; jt++) {
        const int buf = jt % 3;
        if (jt + 2 < NT) stage((jt + 2) % 3, jt + 2);   // ring slot (jt-1)%3

        const uint32_t kbase = ks_addr + buf * TILE_H * 2 + qk_off;
        const uint32_t vbase = vs_addr + buf * TILE_H * 2 + pv_off;

        // ---- S = Q @ K^T (log2-scaled) ----
        float s[8][4];
#pragma unroll
        for (int nt = 0; nt < 8; nt++) { s[nt][0] = s[nt][1] = s[nt][2] = s[nt][3] = 0.0f; }
#pragma unroll
        for (int kk = 0; kk < 4; kk++) {
#pragma unroll
            for (int ntp = 0; ntp < 4; ntp++) {
                uint32_t r[4];
                ldsm4(r, kbase + (ntp * 16 * LDH + kk * 16) * 2);
                mma_f16(s[2 * ntp],     qa[kk], r[0], r[1]);
                mma_f16(s[2 * ntp + 1], qa[kk], r[2], r[3]);
            }
        }

        // ---- online softmax (log2 domain) ----
        float mx0 = -1e30f, mx1 = -1e30f;
#pragma unroll
        for (int nt = 0; nt < 8; nt++) {
            mx0 = fmaxf(mx0, fmaxf(s[nt][0], s[nt][1]));
            mx1 = fmaxf(mx1, fmaxf(s[nt][2], s[nt][3]));
        }
        mx0 = fmaxf(mx0, __shfl_xor_sync(0xffffffffu, mx0, 1));
        mx0 = fmaxf(mx0, __shfl_xor_sync(0xffffffffu, mx0, 2));
        mx1 = fmaxf(mx1, __shfl_xor_sync(0xffffffffu, mx1, 1));
        mx1 = fmaxf(mx1, __shfl_xor_sync(0xffffffffu, mx1, 2));

        float mn0 = fmaxf(m0, mx0), mn1 = fmaxf(m1, mx1);
        float sc0 = exp2f(m0 - mn0), sc1 = exp2f(m1 - mn1);
        m0 = mn0; m1 = mn1;
        const __half2 mh0 = __float2half2_rn(mn0);
        const __half2 mh1 = __float2half2_rn(mn1);

        uint32_t pa[4][4];
#pragma unroll
        for (int t = 0; t < 4; t++) {
            pa[t][0] = ex2_h2(h2u(__hsub2(__floats2half2_rn(s[2*t][0],   s[2*t][1]),   mh0)));
            pa[t][1] = ex2_h2(h2u(__hsub2(__floats2half2_rn(s[2*t][2],   s[2*t][3]),   mh1)));
            pa[t][2] = ex2_h2(h2u(__hsub2(__floats2half2_rn(s[2*t+1][0], s[2*t+1][1]), mh0)));
            pa[t][3] = ex2_h2(h2u(__hsub2(__floats2half2_rn(s[2*t+1][2], s[2*t+1][3]), mh1)));
        }

#pragma unroll
        for (int nt = 0; nt < 8; nt++) {
            o[nt][0] *= sc0; o[nt][1] *= sc0;
            o[nt][2] *= sc1; o[nt][3] *= sc1;
        }
        lacc[0] *= sc0; lacc[1] *= sc0;
        lacc[2] *= sc1; lacc[3] *= sc1;

        // ---- O += P @ V ; l += P @ ones ----
#pragma unroll
        for (int t = 0; t < 4; t++) {
            mma_f16(lacc, pa[t], ONES_H2, ONES_H2);
#pragma unroll
            for (int ntp = 0; ntp < 4; ntp++) {
                uint32_t r[4];
                ldsm4t(r, vbase + (t * 16 * LDH + ntp * 16) * 2);
                mma_f16(o[2 * ntp],     pa[t], r[0], r[1]);
                mma_f16(o[2 * ntp + 1], pa[t], r[2], r[3]);
            }
        }

        if (jt + 1 < NT) {
            if (jt + 2 < NT) cp_wait<1>();
            else             cp_wait<0>();
            __syncthreads();   // the ONE barrier per iteration
        }
    }

    {
        int b = bh >> 4, h = bh & 15;
        float inv0 = 1.0f / lacc[0];
        float inv1 = 1.0f / lacc[2];
        __half* out0 = g_attnh + ((size_t)(b * SS + qrow + gr))     * DM + h * DK;
        __half* out1 = g_attnh + ((size_t)(b * SS + qrow + gr + 8)) * DM + h * DK;
#pragma unroll
        for (int nt = 0; nt < 8; nt++) {
            *(__half2*)&out0[nt * 8 + gc * 2] = __floats2half2_rn(o[nt][0] * inv0, o[nt][1] * inv0);
            *(__half2*)&out1[nt * 8 + gc * 2] = __floats2half2_rn(o[nt][2] * inv1, o[nt][3] * inv1);
        }
    }
}

// ---------------------------------------------------------------------------
// Launcher. Inputs (metadata order): x, Wq, bq, Wk, bk, Wv, bv, Wo, bo
// ---------------------------------------------------------------------------
extern "C" void kernel_launch(void* const* d_in, const int* in_sizes, int n_in,
                              void* d_out, int out_size)
{
    const float* x  = (const float*)d_in[0];
    const float* Wq = (const float*)d_in[1];
    const float* bq = (const float*)d_in[2];
    const float* Wk = (const float*)d_in[3];
    const float* bk = (const float*)d_in[4];
    const float* Wv = (const float*)d_in[5];
    const float* bv = (const float*)d_in[6];
    const float* Wo = (const float*)d_in[7];
    const float* bo = (const float*)d_in[8];
    float* out = (float*)d_out;

    cudaFuncSetAttribute(gemm_f16_kernel<1>,
                         cudaFuncAttributeMaxDynamicSharedMemorySize, GEMM_SMEM_BYTES);
    cudaFuncSetAttribute(gemm_f16_kernel<0>,
                         cudaFuncAttributeMaxDynamicSharedMemorySize, GEMM_SMEM_BYTES);
    cudaFuncSetAttribute(flash_attn_kernel,
                         cudaFuncAttributeMaxDynamicSharedMemorySize, FLASH_SMEM_BYTES);

    // 0) fp32 -> fp16 conversions
    {
        int n8x = (MTOT * DM) / 8;
        f2h_x_kernel<<<n8x / 256, 256>>>(x, n8x);
        int n8w4 = 4 * (DM * DM) / 8;
        f2h_w_kernel<<<n8w4 / 256, 256>>>(Wq, Wk, Wv, Wo);
    }
    // 1) QKV projections
    {
        dim3 grid(DM / 128, MTOT / 128, 3);
        gemm_f16_kernel<1><<<grid, 256, GEMM_SMEM_BYTES>>>(bq, bk, bv, nullptr);
    }
    // 2) flash attention
    {
        dim3 grid(SS / 128, BB * HEADS);
        flash_attn_kernel<<<grid, 256, FLASH_SMEM_BYTES>>>();
    }
    // 3) output projection
    {
        dim3 grid(DM / 128, MTOT / 128, 1);
        gemm_f16_kernel<0><<<grid, 256, GEMM_SMEM_BYTES>>>(bo, nullptr, nullptr, out);
    }
}

// round 16
// speedup vs baseline: 1.0209x; 1.0209x over previous
#include <cuda_runtime.h>
#include <cuda_fp16.h>
#include <cstdint>

// Problem constants
#define DM    1024          // d_model
#define HEADS 16
#define DK    64            // head dim
#define BB    4             // batch
#define SS    2048          // seq len
#define MTOT  (BB * SS)     // 8192 rows

// ---------------------------------------------------------------------------
// Scratch (device globals — no cudaMalloc allowed).
// NOTE (R7 lesson): tcgen05/TMEM unavailable — harness PTX target is sm_103
// (no 'a'). Legacy HMMA only.
// ---------------------------------------------------------------------------
__device__ __half g_xh[(size_t)MTOT * DM];      // x in fp16
__device__ __half g_Wh[4][(size_t)DM * DM];     // Wq, Wk, Wv, Wo in fp16
__device__ __half g_Qh[(size_t)MTOT * DM];      // (B,H,S,DK)
__device__ __half g_Kh[(size_t)MTOT * DM];      // (B,H,S,DK)
__device__ __half g_Vh[(size_t)MTOT * DM];      // (B,H,S,DK)
__device__ __half g_attnh[(size_t)MTOT * DM];   // (B,S,D)

// ---------------------------------------------------------------------------
// Helpers
// ---------------------------------------------------------------------------
__device__ __forceinline__ uint32_t h2u(__half2 h) {
    return *reinterpret_cast<uint32_t*>(&h);
}
__device__ __forceinline__ void cp_async16(void* smem_ptr, const void* gptr) {
    uint32_t sa = (uint32_t)__cvta_generic_to_shared(smem_ptr);
    asm volatile("cp.async.cg.shared.global [%0], [%1], 16;\n" :: "r"(sa), "l"(gptr));
}
__device__ __forceinline__ void cp_commit() {
    asm volatile("cp.async.commit_group;\n");
}
template <int N>
__device__ __forceinline__ void cp_wait() {
    asm volatile("cp.async.wait_group %0;\n" :: "n"(N));
}

// mma.m16n8k16 fp16: C(16x8,f32) += A(16x16,row) * B(16x8,col)
__device__ __forceinline__ void mma_f16(float c[4], const uint32_t a[4],
                                        uint32_t b0, uint32_t b1) {
    asm volatile(
        "mma.sync.aligned.m16n8k16.row.col.f32.f16.f16.f32 "
        "{%0,%1,%2,%3}, {%4,%5,%6,%7}, {%8,%9}, {%0,%1,%2,%3};"
        : "+f"(c[0]), "+f"(c[1]), "+f"(c[2]), "+f"(c[3])
        : "r"(a[0]), "r"(a[1]), "r"(a[2]), "r"(a[3]), "r"(b0), "r"(b1));
}

__device__ __forceinline__ void ldsm4(uint32_t r[4], uint32_t addr) {
    asm volatile("ldmatrix.sync.aligned.m8n8.x4.shared.b16 {%0,%1,%2,%3}, [%4];"
        : "=r"(r[0]), "=r"(r[1]), "=r"(r[2]), "=r"(r[3]) : "r"(addr));
}
__device__ __forceinline__ void ldsm4t(uint32_t r[4], uint32_t addr) {
    asm volatile("ldmatrix.sync.aligned.m8n8.x4.trans.shared.b16 {%0,%1,%2,%3}, [%4];"
        : "=r"(r[0]), "=r"(r[1]), "=r"(r[2]), "=r"(r[3]) : "r"(addr));
}
__device__ __forceinline__ uint32_t ex2_h2(uint32_t x) {
    uint32_t r;
    asm("ex2.approx.f16x2 %0, %1;" : "=r"(r) : "r"(x));
    return r;
}

// ---------------------------------------------------------------------------
// Conversions
// ---------------------------------------------------------------------------
__device__ __forceinline__ void cvt8(const float* __restrict__ src, __half* dst, int i)
{
    const float4* s4 = (const float4*)src;
    float4 v0 = s4[i * 2];
    float4 v1 = s4[i * 2 + 1];
    __half2 h[4];
    h[0] = __floats2half2_rn(v0.x, v0.y);
    h[1] = __floats2half2_rn(v0.z, v0.w);
    h[2] = __floats2half2_rn(v1.x, v1.y);
    h[3] = __floats2half2_rn(v1.z, v1.w);
    *(uint4*)&dst[(size_t)i * 8] = *(uint4*)h;
}

__global__ void f2h_x_kernel(const float* __restrict__ x, int n8)
{
    int i = blockIdx.x * blockDim.x + threadIdx.x;
    if (i < n8) cvt8(x, g_xh, i);
}

__global__ void f2h_w_kernel(const float* __restrict__ W0, const float* __restrict__ W1,
                             const float* __restrict__ W2, const float* __restrict__ W3)
{
    const int n8w = (DM * DM) / 8;
    int i = blockIdx.x * blockDim.x + threadIdx.x;
    int w = i / n8w, r = i - w * n8w;
    const float* src = (w == 0) ? W0 : (w == 1) ? W1 : (w == 2) ? W2 : W3;
    cvt8(src, g_Wh[w], r);
}

// ---------------------------------------------------------------------------
// GEMM (R14 exact — measured best): 2-stage cp.async, register-double-
// buffered fragments, raw mma + ldmatrix, direct register epilogue.
// 128x128 block, KT=64, 8 warps, 2 CTAs/SM (71.7KB SMEM/CTA keeps L1 alive;
// the R15 3-stage ring at 107.5KB/CTA starved L1D and regressed).
// ---------------------------------------------------------------------------
#define KT      64
#define LDA_H   72
#define LDB_H   136
#define A_BUFH  (128 * LDA_H)
#define B_BUFH  (KT * LDB_H)
#define GEMM_SMEM_BYTES ((2 * A_BUFH + 2 * B_BUFH) * (int)sizeof(__half))

template <int MODE>
__global__ __launch_bounds__(256, 2)
void gemm_f16_kernel(const float* __restrict__ b0p,
                     const float* __restrict__ b1p,
                     const float* __restrict__ b2p,
                     float* __restrict__ Cout)
{
    extern __shared__ __half smh[];
    __half* As = smh;
    __half* Bs = smh + 2 * A_BUFH;

    const int z = blockIdx.z;
    const __half* A = (MODE == 0) ? (const __half*)g_attnh : (const __half*)g_xh;
    const __half* W = (MODE == 0) ? g_Wh[3] : g_Wh[z];
    const float* bias = (MODE == 0) ? b0p : (z == 0 ? b0p : (z == 1 ? b1p : b2p));
    __half* Ch = (MODE == 0) ? nullptr : (z == 0 ? g_Qh : (z == 1 ? g_Kh : g_Vh));

    const int tid  = threadIdx.x;
    const int warp = tid >> 5;
    const int lane = tid & 31;
    const int gr   = lane >> 2;
    const int gc   = lane & 3;
    const int wm   = warp >> 1;
    const int wn   = warp & 1;
    const int m0   = blockIdx.y * 128;
    const int n0   = blockIdx.x * 128;

    auto stage = [&](int buf, int k0) {
        __half* ad = As + buf * A_BUFH;
        __half* bd = Bs + buf * B_BUFH;
#pragma unroll
        for (int t = 0; t < 4; t++) {
            int id = tid + t * 256;
            int r = id >> 3, c = (id & 7) * 8;
            cp_async16(&ad[r * LDA_H + c], &A[(size_t)(m0 + r) * DM + k0 + c]);
        }
#pragma unroll
        for (int t = 0; t < 4; t++) {
            int id = tid + t * 256;
            int r = id >> 4, c = (id & 15) * 8;
            cp_async16(&bd[r * LDB_H + c], &W[(size_t)(k0 + r) * DM + n0 + c]);
        }
        cp_commit();
    };

    float acc[2][8][4];
#pragma unroll
    for (int im = 0; im < 2; im++)
#pragma unroll
        for (int nt = 0; nt < 8; nt++)
            acc[im][nt][0] = acc[im][nt][1] = acc[im][nt][2] = acc[im][nt][3] = 0.0f;

    const uint32_t as_addr = (uint32_t)__cvta_generic_to_shared(As);
    const uint32_t bs_addr = (uint32_t)__cvta_generic_to_shared(Bs);
    const uint32_t a_off = (((lane & 15) * LDA_H) + ((lane >> 4) * 8)) * 2;
    const uint32_t b_off = (((lane & 15) * LDB_H) + ((lane & 16) >> 1)) * 2;

    stage(0, 0);

    uint32_t afr[2][2][4];
    uint32_t bfr[2][4][4];

    const int NT = DM / KT;   // 16
    for (int t = 0; t < NT; t++) {
        int buf = t & 1;
        if (t + 1 < NT) {
            stage(buf ^ 1, (t + 1) * KT);
            cp_wait<1>();
        } else {
            cp_wait<0>();
        }
        __syncthreads();

        const uint32_t abase = as_addr + buf * A_BUFH * 2 + a_off + (wm * 32 * LDA_H) * 2;
        const uint32_t bbase = bs_addr + buf * B_BUFH * 2 + b_off + (wn * 64) * 2;

        ldsm4(afr[0][0], abase);
        ldsm4(afr[0][1], abase + (16 * LDA_H) * 2);
#pragma unroll
        for (int ntp = 0; ntp < 4; ntp++)
            ldsm4t(bfr[0][ntp], bbase + (ntp * 16) * 2);

#pragma unroll
        for (int ks = 0; ks < 4; ks++) {
            const int cur = ks & 1, nxt = cur ^ 1;
            if (ks < 3) {
                ldsm4(afr[nxt][0], abase + ((ks + 1) * 16) * 2);
                ldsm4(afr[nxt][1], abase + (16 * LDA_H + (ks + 1) * 16) * 2);
#pragma unroll
                for (int ntp = 0; ntp < 4; ntp++)
                    ldsm4t(bfr[nxt][ntp], bbase + ((ks + 1) * 16 * LDB_H + ntp * 16) * 2);
            }
#pragma unroll
            for (int ntp = 0; ntp < 4; ntp++) {
                mma_f16(acc[0][2 * ntp],     afr[cur][0], bfr[cur][ntp][0], bfr[cur][ntp][1]);
                mma_f16(acc[0][2 * ntp + 1], afr[cur][0], bfr[cur][ntp][2], bfr[cur][ntp][3]);
                mma_f16(acc[1][2 * ntp],     afr[cur][1], bfr[cur][ntp][0], bfr[cur][ntp][1]);
                mma_f16(acc[1][2 * ntp + 1], afr[cur][1], bfr[cur][ntp][2], bfr[cur][ntp][3]);
            }
        }
        __syncthreads();
    }

    float bv0[8], bv1[8];
#pragma unroll
    for (int nt = 0; nt < 8; nt++) {
        int gn = n0 + wn * 64 + nt * 8 + gc * 2;
        bv0[nt] = bias[gn];
        bv1[nt] = bias[gn + 1];
    }

#pragma unroll
    for (int im = 0; im < 2; im++) {
        int gm0 = m0 + wm * 32 + im * 16 + gr;
        int gm1 = gm0 + 8;
        if (MODE == 0) {
            float* d0 = Cout + (size_t)gm0 * DM + n0 + wn * 64 + gc * 2;
            float* d1 = Cout + (size_t)gm1 * DM + n0 + wn * 64 + gc * 2;
#pragma unroll
            for (int nt = 0; nt < 8; nt++) {
                *(float2*)&d0[nt * 8] = make_float2(acc[im][nt][0] + bv0[nt],
                                                    acc[im][nt][1] + bv1[nt]);
                *(float2*)&d1[nt * 8] = make_float2(acc[im][nt][2] + bv0[nt],
                                                    acc[im][nt][3] + bv1[nt]);
            }
        } else {
            int h  = (n0 + wn * 64) >> 6;
            int b0i = gm0 >> 11, s0 = gm0 & 2047;
            int b1i = gm1 >> 11, s1 = gm1 & 2047;
            __half* d0 = Ch + (((size_t)(b0i * HEADS + h)) * SS + s0) * DK + gc * 2;
            __half* d1 = Ch + (((size_t)(b1i * HEADS + h)) * SS + s1) * DK + gc * 2;
#pragma unroll
            for (int nt = 0; nt < 8; nt++) {
                *(__half2*)&d0[nt * 8] = __floats2half2_rn(acc[im][nt][0] + bv0[nt],
                                                           acc[im][nt][1] + bv1[nt]);
                *(__half2*)&d1[nt * 8] = __floats2half2_rn(acc[im][nt][2] + bv0[nt],
                                                           acc[im][nt][3] + bv1[nt]);
            }
        }
    }
}

// ---------------------------------------------------------------------------
// Flash attention (R15 exact — measured best, 199.6us): 128 q-rows/CTA,
// 8 warps x 16 rows, 2 CTAs/SM, 3-STAGE K/V ring with ONE barrier per
// key-tile, ldmatrix, log2-softmax via ex2.approx.f16x2, l via ones-HMMA.
// ---------------------------------------------------------------------------
#define LDH    72
#define TILE_H (64 * LDH)
#define FLASH_SMEM_BYTES (6 * TILE_H * (int)sizeof(__half))   // 3 stages x (K+V)
#define ONES_H2 0x3C003C00u

__global__ __launch_bounds__(256, 2)
void flash_attn_kernel()
{
    extern __shared__ __half smf[];
    __half* KsB = smf;                 // [3][TILE_H]
    __half* VsB = smf + 3 * TILE_H;    // [3][TILE_H]

    const int tid  = threadIdx.x;
    const int warp = tid >> 5;
    const int lane = tid & 31;
    const int gr   = lane >> 2;
    const int gc   = lane & 3;
    const int qt   = blockIdx.x;
    const int bh   = blockIdx.y;

    const __half* Qb = g_Qh + (size_t)bh * SS * DK;
    const __half* Kb = g_Kh + (size_t)bh * SS * DK;
    const __half* Vb = g_Vh + (size_t)bh * SS * DK;

    const int qrow = qt * 128 + warp * 16;

    const __half2 sc2 = __float2half2_rn(0.125f * 1.4426950408889634f);
    uint32_t qa[4][4];
#pragma unroll
    for (int kk = 0; kk < 4; kk++) {
        const __half* q0 = Qb + (size_t)(qrow + gr)     * DK + kk * 16 + 2 * gc;
        const __half* q1 = Qb + (size_t)(qrow + gr + 8) * DK + kk * 16 + 2 * gc;
        qa[kk][0] = h2u(__hmul2(*(const __half2*)(q0),     sc2));
        qa[kk][1] = h2u(__hmul2(*(const __half2*)(q1),     sc2));
        qa[kk][2] = h2u(__hmul2(*(const __half2*)(q0 + 8), sc2));
        qa[kk][3] = h2u(__hmul2(*(const __half2*)(q1 + 8), sc2));
    }

    float o[8][4];
#pragma unroll
    for (int nt = 0; nt < 8; nt++) { o[nt][0] = o[nt][1] = o[nt][2] = o[nt][3] = 0.0f; }
    float lacc[4] = {0.0f, 0.0f, 0.0f, 0.0f};
    float m0 = -1e30f, m1 = -1e30f;

    const uint32_t ks_addr = (uint32_t)__cvta_generic_to_shared(KsB);
    const uint32_t vs_addr = (uint32_t)__cvta_generic_to_shared(VsB);
    const uint32_t qk_off = ((((lane & 7) | ((lane & 16) >> 1)) * LDH) + (lane & 8)) * 2;
    const uint32_t pv_off = (((lane & 15) * LDH) + ((lane & 16) >> 1)) * 2;

    auto stage = [&](int buf, int jt) {
        const __half* Kt = Kb + (size_t)(jt * 64) * DK;
        const __half* Vt = Vb + (size_t)(jt * 64) * DK;
        __half* kd = KsB + buf * TILE_H;
        __half* vd = VsB + buf * TILE_H;
#pragma unroll
        for (int rp = 0; rp < 2; rp++) {
            int id = tid + rp * 256;
            int row = id >> 3, c8 = (id & 7) * 8;
            cp_async16(&kd[row * LDH + c8], &Kt[(size_t)row * DK + c8]);
            cp_async16(&vd[row * LDH + c8], &Vt[(size_t)row * DK + c8]);
        }
        cp_commit();
    };

    stage(0, 0);
    stage(1, 1);
    cp_wait<1>();        // tile 0 ready
    __syncthreads();

    const int NT = SS / 64;   // 32
    for (int jt = 0; jt < NT; jt++) {
        const int buf = jt % 3;
        if (jt + 2 < NT) stage((jt + 2) % 3, jt + 2);

        const uint32_t kbase = ks_addr + buf * TILE_H * 2 + qk_off;
        const uint32_t vbase = vs_addr + buf * TILE_H * 2 + pv_off;

        float s[8][4];
#pragma unroll
        for (int nt = 0; nt < 8; nt++) { s[nt][0] = s[nt][1] = s[nt][2] = s[nt][3] = 0.0f; }
#pragma unroll
        for (int kk = 0; kk < 4; kk++) {
#pragma unroll
            for (int ntp = 0; ntp < 4; ntp++) {
                uint32_t r[4];
                ldsm4(r, kbase + (ntp * 16 * LDH + kk * 16) * 2);
                mma_f16(s[2 * ntp],     qa[kk], r[0], r[1]);
                mma_f16(s[2 * ntp + 1], qa[kk], r[2], r[3]);
            }
        }

        float mx0 = -1e30f, mx1 = -1e30f;
#pragma unroll
        for (int nt = 0; nt < 8; nt++) {
            mx0 = fmaxf(mx0, fmaxf(s[nt][0], s[nt][1]));
            mx1 = fmaxf(mx1, fmaxf(s[nt][2], s[nt][3]));
        }
        mx0 = fmaxf(mx0, __shfl_xor_sync(0xffffffffu, mx0, 1));
        mx0 = fmaxf(mx0, __shfl_xor_sync(0xffffffffu, mx0, 2));
        mx1 = fmaxf(mx1, __shfl_xor_sync(0xffffffffu, mx1, 1));
        mx1 = fmaxf(mx1, __shfl_xor_sync(0xffffffffu, mx1, 2));

        float mn0 = fmaxf(m0, mx0), mn1 = fmaxf(m1, mx1);
        float sc0 = exp2f(m0 - mn0), sc1 = exp2f(m1 - mn1);
        m0 = mn0; m1 = mn1;
        const __half2 mh0 = __float2half2_rn(mn0);
        const __half2 mh1 = __float2half2_rn(mn1);

        uint32_t pa[4][4];
#pragma unroll
        for (int t = 0; t < 4; t++) {
            pa[t][0] = ex2_h2(h2u(__hsub2(__floats2half2_rn(s[2*t][0],   s[2*t][1]),   mh0)));
            pa[t][1] = ex2_h2(h2u(__hsub2(__floats2half2_rn(s[2*t][2],   s[2*t][3]),   mh1)));
            pa[t][2] = ex2_h2(h2u(__hsub2(__floats2half2_rn(s[2*t+1][0], s[2*t+1][1]), mh0)));
            pa[t][3] = ex2_h2(h2u(__hsub2(__floats2half2_rn(s[2*t+1][2], s[2*t+1][3]), mh1)));
        }

#pragma unroll
        for (int nt = 0; nt < 8; nt++) {
            o[nt][0] *= sc0; o[nt][1] *= sc0;
            o[nt][2] *= sc1; o[nt][3] *= sc1;
        }
        lacc[0] *= sc0; lacc[1] *= sc0;
        lacc[2] *= sc1; lacc[3] *= sc1;

#pragma unroll
        for (int t = 0; t < 4; t++) {
            mma_f16(lacc, pa[t], ONES_H2, ONES_H2);
#pragma unroll
            for (int ntp = 0; ntp < 4; ntp++) {
                uint32_t r[4];
                ldsm4t(r, vbase + (t * 16 * LDH + ntp * 16) * 2);
                mma_f16(o[2 * ntp],     pa[t], r[0], r[1]);
                mma_f16(o[2 * ntp + 1], pa[t], r[2], r[3]);
            }
        }

        if (jt + 1 < NT) {
            if (jt + 2 < NT) cp_wait<1>();
            else             cp_wait<0>();
            __syncthreads();
        }
    }

    {
        int b = bh >> 4, h = bh & 15;
        float inv0 = 1.0f / lacc[0];
        float inv1 = 1.0f / lacc[2];
        __half* out0 = g_attnh + ((size_t)(b * SS + qrow + gr))     * DM + h * DK;
        __half* out1 = g_attnh + ((size_t)(b * SS + qrow + gr + 8)) * DM + h * DK;
#pragma unroll
        for (int nt = 0; nt < 8; nt++) {
            *(__half2*)&out0[nt * 8 + gc * 2] = __floats2half2_rn(o[nt][0] * inv0, o[nt][1] * inv0);
            *(__half2*)&out1[nt * 8 + gc * 2] = __floats2half2_rn(o[nt][2] * inv1, o[nt][3] * inv1);
        }
    }
}

// ---------------------------------------------------------------------------
// Launcher. Inputs (metadata order): x, Wq, bq, Wk, bk, Wv, bv, Wo, bo
// ---------------------------------------------------------------------------
extern "C" void kernel_launch(void* const* d_in, const int* in_sizes, int n_in,
                              void* d_out, int out_size)
{
    const float* x  = (const float*)d_in[0];
    const float* Wq = (const float*)d_in[1];
    const float* bq = (const float*)d_in[2];
    const float* Wk = (const float*)d_in[3];
    const float* bk = (const float*)d_in[4];
    const float* Wv = (const float*)d_in[5];
    const float* bv = (const float*)d_in[6];
    const float* Wo = (const float*)d_in[7];
    const float* bo = (const float*)d_in[8];
    float* out = (float*)d_out;

    cudaFuncSetAttribute(gemm_f16_kernel<1>,
                         cudaFuncAttributeMaxDynamicSharedMemorySize, GEMM_SMEM_BYTES);
    cudaFuncSetAttribute(gemm_f16_kernel<0>,
                         cudaFuncAttributeMaxDynamicSharedMemorySize, GEMM_SMEM_BYTES);
    cudaFuncSetAttribute(flash_attn_kernel,
                         cudaFuncAttributeMaxDynamicSharedMemorySize, FLASH_SMEM_BYTES);

    // 0) fp32 -> fp16 conversions
    {
        int n8x = (MTOT * DM) / 8;
        f2h_x_kernel<<<n8x / 256, 256>>>(x, n8x);
        int n8w4 = 4 * (DM * DM) / 8;
        f2h_w_kernel<<<n8w4 / 256, 256>>>(Wq, Wk, Wv, Wo);
    }
    // 1) QKV projections
    {
        dim3 grid(DM / 128, MTOT / 128, 3);
        gemm_f16_kernel<1><<<grid, 256, GEMM_SMEM_BYTES>>>(bq, bk, bv, nullptr);
    }
    // 2) flash attention
    {
        dim3 grid(SS / 128, BB * HEADS);
        flash_attn_kernel<<<grid, 256, FLASH_SMEM_BYTES>>>();
    }
    // 3) output projection
    {
        dim3 grid(DM / 128, MTOT / 128, 1);
        gemm_f16_kernel<0><<<grid, 256, GEMM_SMEM_BYTES>>>(bo, nullptr, nullptr, out);
    }
}